// round 1
// baseline (speedup 1.0000x reference)
#include <cuda_runtime.h>
#include <cuda_bf16.h>
#include <math.h>

#define BATCH 4
#define SEQ 1024
#define NTOK (BATCH*SEQ)
#define EMB 512
#define CDIM 256
#define NLAYER 6
#define NHEAD 8
#define HDIM 32
#define IDIM 1024
#define VOCAB 50304

// -------------------- scratch (static device allocations) --------------------
__device__ float g_tok[NTOK*EMB];
__device__ float g_pre[NTOK*CDIM];
__device__ float g_x[NTOK*CDIM];
__device__ float g_a[NTOK*CDIM];
__device__ float g_m[NTOK*CDIM];
__device__ float g_qkv[NTOK*3*CDIM];
__device__ float g_o[NTOK*CDIM];
__device__ float g_h1[NTOK*IDIM];
__device__ float4 g_Wt4[64*CDIM];   // ctx_w[:, :256] transposed, packed by 4 j's

__device__ __forceinline__ float gelu_f(float x){
  float x3 = x*x*x;
  return 0.5f*x*(1.0f + tanhf(0.7978845608028654f*(x + 0.044715f*x3)));
}

// -------------------- embed gather + LayerNorm(E=512) --------------------
__global__ void embed_ln_kernel(const int* __restrict__ ids, const float* __restrict__ emb,
                                const float* __restrict__ w, const float* __restrict__ b){
  int t = blockIdx.x;
  int tid = threadIdx.x;
  int lane = tid & 31, wid = tid >> 5;
  __shared__ float red[16];
  int id = ids[t];
  const float* row = emb + (size_t)id*EMB;
  float v0 = row[tid], v1 = row[tid+256];
  float s = v0+v1, s2 = v0*v0+v1*v1;
  #pragma unroll
  for (int o=16;o>0;o>>=1){ s += __shfl_xor_sync(0xffffffffu,s,o); s2 += __shfl_xor_sync(0xffffffffu,s2,o); }
  if (lane==0){ red[wid]=s; red[8+wid]=s2; }
  __syncthreads();
  if (tid==0){ float aa=0,cc=0; for(int i=0;i<8;i++){aa+=red[i]; cc+=red[8+i];} red[0]=aa; red[8]=cc; }
  __syncthreads();
  float mean = red[0]*(1.0f/EMB);
  float var  = red[8]*(1.0f/EMB) - mean*mean;
  float rstd = rsqrtf(var + 1e-5f);
  g_tok[(size_t)t*EMB + tid]       = (v0-mean)*rstd*w[tid]     + b[tid];
  g_tok[(size_t)t*EMB + tid + 256] = (v1-mean)*rstd*w[tid+256] + b[tid+256];
}

// -------------------- LayerNorm over C=256 --------------------
__global__ void ln256_kernel(const float* __restrict__ in, const float* __restrict__ w,
                             const float* __restrict__ b, float* __restrict__ out){
  int t = blockIdx.x, tid = threadIdx.x;
  int lane = tid & 31, wid = tid >> 5;
  __shared__ float red[16];
  float v = in[(size_t)t*CDIM + tid];
  float s = v, s2 = v*v;
  #pragma unroll
  for (int o=16;o>0;o>>=1){ s += __shfl_xor_sync(0xffffffffu,s,o); s2 += __shfl_xor_sync(0xffffffffu,s2,o); }
  if (lane==0){ red[wid]=s; red[8+wid]=s2; }
  __syncthreads();
  if (tid==0){ float aa=0,cc=0; for(int i=0;i<8;i++){aa+=red[i]; cc+=red[8+i];} red[0]=aa; red[8]=cc; }
  __syncthreads();
  float mean = red[0]*(1.0f/CDIM);
  float var  = red[8]*(1.0f/CDIM) - mean*mean;
  float rstd = rsqrtf(var + 1e-5f);
  out[(size_t)t*CDIM + tid] = (v-mean)*rstd*w[tid] + b[tid];
}

// -------------------- transpose+pack ctx_w[:, :256] --------------------
__global__ void transpose_w_kernel(const float* __restrict__ ctx_w){
  int o = threadIdx.x, j4 = blockIdx.x;   // 64 blocks x 256 threads
  const float* r = ctx_w + (size_t)o*768 + j4*4;
  g_Wt4[j4*CDIM + o] = make_float4(r[0], r[1], r[2], r[3]);
}

// -------------------- sequential context scan: 1 CTA per batch --------------------
__global__ void scan_kernel(const float* __restrict__ prev, const float* __restrict__ cw,
                            const float* __restrict__ cb){
  int b = blockIdx.x, tid = threadIdx.x;
  int lane = tid & 31, wid = tid >> 5;
  __shared__ float4 ctx4[64];
  __shared__ float red[16];
  __shared__ float stat[2];
  float w_ = cw[tid], b_ = cb[tid];
  ((float*)ctx4)[tid] = prev[b*CDIM + tid];
  __syncthreads();
  for (int t=0; t<SEQ; t++){
    float acc = g_pre[(size_t)(b*SEQ+t)*CDIM + tid];
    float s0=0.f, s1=0.f, s2=0.f, s3=0.f;
    #pragma unroll
    for (int j=0;j<64;j++){
      float4 wv = g_Wt4[j*CDIM + tid];
      float4 c  = ctx4[j];
      s0 = fmaf(wv.x, c.x, s0); s1 = fmaf(wv.y, c.y, s1);
      s2 = fmaf(wv.z, c.z, s2); s3 = fmaf(wv.w, c.w, s3);
    }
    acc += (s0+s1)+(s2+s3);
    float g = gelu_f(acc);
    float rs = g, rq = g*g;
    #pragma unroll
    for (int o=16;o>0;o>>=1){ rs += __shfl_xor_sync(0xffffffffu,rs,o); rq += __shfl_xor_sync(0xffffffffu,rq,o); }
    if (lane==0){ red[wid]=rs; red[8+wid]=rq; }
    __syncthreads();
    if (tid==0){
      float aa=0,cc=0; for(int i=0;i<8;i++){aa+=red[i]; cc+=red[8+i];}
      float mean = aa*(1.0f/CDIM);
      float var  = cc*(1.0f/CDIM) - mean*mean;
      stat[0]=mean; stat[1]=rsqrtf(var + 1e-5f);
    }
    __syncthreads();
    float y = (g - stat[0])*stat[1]*w_ + b_;
    g_x[(size_t)(b*SEQ+t)*CDIM + tid] = y;
    ((float*)ctx4)[tid] = y;
    __syncthreads();
  }
}

// -------------------- RoPE (in-place on q,k; ROT=8, half=4) --------------------
__global__ void rope_kernel(){
  int idx = blockIdx.x*blockDim.x + threadIdx.x;
  if (idx >= NTOK*NHEAD*2) return;
  int qk = idx & 1;
  int h  = (idx>>1) & 7;
  int t  = idx >> 4;
  int pos = t & (SEQ-1);
  float* p = g_qkv + (size_t)t*768 + qk*CDIM + h*HDIM;
  #pragma unroll
  for (int i=0;i<4;i++){
    float inv = 1.0f/powf(10000.0f, (float)(2*i)/8.0f);
    float ang = (float)pos * inv;
    float c = cosf(ang), s = sinf(ang);
    float x0 = p[i], x1 = p[i+4];
    p[i]   = x0*c - x1*s;
    p[i+4] = x1*c + x0*s;
  }
}

// -------------------- causal attention: 1 warp per query row --------------------
__global__ __launch_bounds__(256) void attn_kernel(){
  int qblk = blockIdx.x, h = blockIdx.y, b = blockIdx.z;
  int tid = threadIdx.x, w = tid >> 5, lane = tid & 31;
  __shared__ float Ks[64][33];
  __shared__ float Vs[64][33];
  int q = qblk*8 + w;
  int qtok = b*SEQ + q;
  const float* qp = g_qkv + (size_t)qtok*768 + h*HDIM;
  const float scale = 0.17677669529663687f; // 1/sqrt(32)
  float qr[32];
  #pragma unroll
  for (int d=0;d<32;d++) qr[d] = qp[d]*scale;
  float m = -1e30f, l = 0.f, acc = 0.f;   // acc holds output dim d = lane
  int ntiles = (qblk*8 + 7)/64 + 1;
  for (int tile=0; tile<ntiles; tile++){
    int k0 = tile*64;
    __syncthreads();
    for (int i=tid; i<64*32; i+=256){
      int r = i>>5, d = i&31;
      const float* kp = g_qkv + (size_t)(b*SEQ + k0 + r)*768;
      Ks[r][d] = kp[CDIM   + h*HDIM + d];
      Vs[r][d] = kp[2*CDIM + h*HDIM + d];
    }
    __syncthreads();
    #pragma unroll
    for (int c0=0; c0<64; c0+=32){
      int k = k0 + c0 + lane;
      float s;
      if (k <= q){
        s = 0.f;
        #pragma unroll
        for (int d=0; d<32; d++) s = fmaf(qr[d], Ks[c0+lane][d], s);
      } else s = -1e30f;
      float mc = s;
      #pragma unroll
      for (int o=16;o>0;o>>=1) mc = fmaxf(mc, __shfl_xor_sync(0xffffffffu, mc, o));
      float mnew = fmaxf(m, mc);
      float corr = expf(m - mnew);
      float p = expf(s - mnew);
      acc *= corr; l *= corr;
      float ps = p;
      #pragma unroll
      for (int o=16;o>0;o>>=1) ps += __shfl_xor_sync(0xffffffffu, ps, o);
      l += ps;
      #pragma unroll
      for (int kk=0; kk<32; kk++){
        float pk = __shfl_sync(0xffffffffu, p, kk);
        acc = fmaf(pk, Vs[c0+kk][lane], acc);
      }
      m = mnew;
    }
  }
  g_o[(size_t)qtok*CDIM + h*HDIM + lane] = acc / l;
}

// -------------------- generic SGEMM: C[M,N] = A[M,K] @ B[N,K]^T (+bias/gelu/residual) ----
// M,N multiples of 128; K multiple of 8. 128x128 tile, 256 threads, 8x8 per thread.
__global__ __launch_bounds__(256,2) void sgemm_kernel(
    const float* __restrict__ A, int lda,
    const float* __restrict__ B, int ldb,
    const float* __restrict__ bias,
    const float* __restrict__ Res,
    float* __restrict__ C, int ldc,
    int K, int mode){ // mode 0: +bias; 1: gelu(+bias); 2: Res + acc + bias
  __shared__ float As[8][132];
  __shared__ float Bs[8][132];
  int tid = threadIdx.x;
  int bm = blockIdx.y*128, bn = blockIdx.x*128;
  int tx = tid & 15, ty = tid >> 4;
  int lRow = tid >> 1, lCol = (tid & 1)*4;
  const float* Ap = A + (size_t)(bm + lRow)*lda + lCol;
  const float* Bp = B + (size_t)(bn + lRow)*ldb + lCol;
  float acc[8][8];
  #pragma unroll
  for (int i=0;i<8;i++)
    #pragma unroll
    for (int j=0;j<8;j++) acc[i][j]=0.f;
  for (int kt=0; kt<K; kt+=8){
    float4 av = *(const float4*)(Ap + kt);
    float4 bv = *(const float4*)(Bp + kt);
    As[lCol+0][lRow]=av.x; As[lCol+1][lRow]=av.y; As[lCol+2][lRow]=av.z; As[lCol+3][lRow]=av.w;
    Bs[lCol+0][lRow]=bv.x; Bs[lCol+1][lRow]=bv.y; Bs[lCol+2][lRow]=bv.z; Bs[lCol+3][lRow]=bv.w;
    __syncthreads();
    #pragma unroll
    for (int k=0;k<8;k++){
      float ar[8], br[8];
      #pragma unroll
      for (int i=0;i<8;i++) ar[i] = As[k][ty*8+i];
      #pragma unroll
      for (int j=0;j<8;j++) br[j] = Bs[k][tx*8+j];
      #pragma unroll
      for (int i=0;i<8;i++)
        #pragma unroll
        for (int j=0;j<8;j++)
          acc[i][j] = fmaf(ar[i], br[j], acc[i][j]);
    }
    __syncthreads();
  }
  #pragma unroll
  for (int i=0;i<8;i++){
    int row = bm + ty*8 + i;
    #pragma unroll
    for (int j0=0;j0<8;j0+=4){
      int col = bn + tx*8 + j0;
      float4 v;
      v.x=acc[i][j0]; v.y=acc[i][j0+1]; v.z=acc[i][j0+2]; v.w=acc[i][j0+3];
      if (bias){
        float4 bb = *(const float4*)(bias+col);
        v.x+=bb.x; v.y+=bb.y; v.z+=bb.z; v.w+=bb.w;
      }
      if (mode==1){ v.x=gelu_f(v.x); v.y=gelu_f(v.y); v.z=gelu_f(v.z); v.w=gelu_f(v.w); }
      else if (mode==2){
        float4 rr = *(const float4*)(Res + (size_t)row*ldc + col);
        v.x+=rr.x; v.y+=rr.y; v.z+=rr.z; v.w+=rr.w;
      }
      *(float4*)(C + (size_t)row*ldc + col) = v;
    }
  }
}

// -------------------- host launch --------------------
static void* sym_addr_f(const void* symbol){
  void* p = nullptr;
  cudaGetSymbolAddress(&p, symbol);
  return p;
}

extern "C" void kernel_launch(void* const* d_in, const int* in_sizes, int n_in,
                              void* d_out, int out_size){
  (void)in_sizes; (void)n_in; (void)out_size;
  const int*   ids     = (const int*)d_in[0];
  const float* prev    = (const float*)d_in[1];
  const float* embed_w = (const float*)d_in[2];
  const float* en_w    = (const float*)d_in[3];
  const float* en_b    = (const float*)d_in[4];
  const float* ctx_w   = (const float*)d_in[5];
  const float* ctx_b   = (const float*)d_in[6];
  const float* cn_w    = (const float*)d_in[7];
  const float* cn_b    = (const float*)d_in[8];
  const float* ln1_w   = (const float*)d_in[9];
  const float* ln1_b   = (const float*)d_in[10];
  const float* ln2_w   = (const float*)d_in[11];
  const float* ln2_b   = (const float*)d_in[12];
  const float* qkv_w   = (const float*)d_in[13];
  const float* qkv_b   = (const float*)d_in[14];
  const float* ao_w    = (const float*)d_in[15];
  const float* ao_b    = (const float*)d_in[16];
  const float* fc1_w   = (const float*)d_in[17];
  const float* fc1_b   = (const float*)d_in[18];
  const float* fc2_w   = (const float*)d_in[19];
  const float* fc2_b   = (const float*)d_in[20];
  const float* fln_w   = (const float*)d_in[21];
  const float* fln_b   = (const float*)d_in[22];
  const float* out_w   = (const float*)d_in[23];
  float* out = (float*)d_out;

  float* tok = (float*)sym_addr_f(g_tok);
  float* pre = (float*)sym_addr_f(g_pre);
  float* x   = (float*)sym_addr_f(g_x);
  float* a   = (float*)sym_addr_f(g_a);
  float* mm  = (float*)sym_addr_f(g_m);
  float* qkv = (float*)sym_addr_f(g_qkv);
  float* ob  = (float*)sym_addr_f(g_o);
  float* h1  = (float*)sym_addr_f(g_h1);

  // embed + LN, weight transpose, emb-part of the scan matmul
  embed_ln_kernel<<<NTOK,256>>>(ids, embed_w, en_w, en_b);
  transpose_w_kernel<<<64,256>>>(ctx_w);
  sgemm_kernel<<<dim3(CDIM/128, NTOK/128),256>>>(tok,EMB, ctx_w+CDIM,CDIM+EMB, ctx_b, nullptr, pre,CDIM, EMB, 0);
  // sequential context RNN
  scan_kernel<<<BATCH,256>>>(prev, cn_w, cn_b);

  for (int l=0;l<NLAYER;l++){
    ln256_kernel<<<NTOK,256>>>(x, ln1_w+l*CDIM, ln1_b+l*CDIM, a);
    ln256_kernel<<<NTOK,256>>>(x, ln2_w+l*CDIM, ln2_b+l*CDIM, mm);
    sgemm_kernel<<<dim3(3*CDIM/128, NTOK/128),256>>>(a,CDIM, qkv_w+(size_t)l*3*CDIM*CDIM,CDIM,
                                                     qkv_b+l*3*CDIM, nullptr, qkv,3*CDIM, CDIM, 0);
    rope_kernel<<<(NTOK*NHEAD*2)/256,256>>>();
    attn_kernel<<<dim3(SEQ/8, NHEAD, BATCH),256>>>();
    sgemm_kernel<<<dim3(IDIM/128, NTOK/128),256>>>(mm,CDIM, fc1_w+(size_t)l*IDIM*CDIM,CDIM,
                                                   fc1_b+l*IDIM, nullptr, h1,IDIM, CDIM, 1);
    sgemm_kernel<<<dim3(CDIM/128, NTOK/128),256>>>(ob,CDIM, ao_w+(size_t)l*CDIM*CDIM,CDIM,
                                                   ao_b+l*CDIM, x, x,CDIM, CDIM, 2);
    sgemm_kernel<<<dim3(CDIM/128, NTOK/128),256>>>(h1,IDIM, fc2_w+(size_t)l*CDIM*IDIM,IDIM,
                                                   fc2_b+l*CDIM, x, x,CDIM, IDIM, 2);
  }

  ln256_kernel<<<NTOK,256>>>(x, fln_w, fln_b, a);
  sgemm_kernel<<<dim3(VOCAB/128, NTOK/128),256>>>(a,CDIM, out_w,CDIM, nullptr, nullptr, out,VOCAB, CDIM, 0);
}

// round 4
// speedup vs baseline: 2.3505x; 2.3505x over previous
#include <cuda_runtime.h>
#include <cuda_bf16.h>
#include <math.h>

#define BATCH 4
#define SEQ 1024
#define NTOK (BATCH*SEQ)
#define EMB 512
#define CDIM 256
#define NLAYER 6
#define NHEAD 8
#define HDIM 32
#define IDIM 1024
#define VOCAB 50304

// -------------------- scratch (static device allocations) --------------------
__device__ float g_tok[NTOK*EMB];
__device__ float g_pre[NTOK*CDIM];
__device__ float g_x[NTOK*CDIM];
__device__ float g_a[NTOK*CDIM];
__device__ float g_m[NTOK*CDIM];
__device__ float g_qkv[NTOK*3*CDIM];
__device__ float g_o[NTOK*CDIM];
__device__ float g_h1[NTOK*IDIM];
__device__ float4 g_Wt4[64*CDIM];   // ctx_w[:, :256] transposed, packed by 4 j's

__device__ __forceinline__ float gelu_f(float x){
  float x3 = x*x*x;
  return 0.5f*x*(1.0f + tanhf(0.7978845608028654f*(x + 0.044715f*x3)));
}

__device__ __forceinline__ unsigned f2tf32(float f){
  unsigned u;
  asm("cvt.rna.tf32.f32 %0, %1;" : "=r"(u) : "f"(f));
  return u;
}

// -------------------- embed gather + LayerNorm(E=512) --------------------
__global__ void embed_ln_kernel(const int* __restrict__ ids, const float* __restrict__ emb,
                                const float* __restrict__ w, const float* __restrict__ b){
  int t = blockIdx.x;
  int tid = threadIdx.x;
  int lane = tid & 31, wid = tid >> 5;
  __shared__ float red[16];
  int id = ids[t];
  const float* row = emb + (size_t)id*EMB;
  float v0 = row[tid], v1 = row[tid+256];
  float s = v0+v1, s2 = v0*v0+v1*v1;
  #pragma unroll
  for (int o=16;o>0;o>>=1){ s += __shfl_xor_sync(0xffffffffu,s,o); s2 += __shfl_xor_sync(0xffffffffu,s2,o); }
  if (lane==0){ red[wid]=s; red[8+wid]=s2; }
  __syncthreads();
  if (tid==0){ float aa=0,cc=0; for(int i=0;i<8;i++){aa+=red[i]; cc+=red[8+i];} red[0]=aa; red[8]=cc; }
  __syncthreads();
  float mean = red[0]*(1.0f/EMB);
  float var  = red[8]*(1.0f/EMB) - mean*mean;
  float rstd = rsqrtf(var + 1e-5f);
  g_tok[(size_t)t*EMB + tid]       = (v0-mean)*rstd*w[tid]     + b[tid];
  g_tok[(size_t)t*EMB + tid + 256] = (v1-mean)*rstd*w[tid+256] + b[tid+256];
}

// -------------------- LayerNorm over C=256 (single output) --------------------
__global__ void ln256_kernel(const float* __restrict__ in, const float* __restrict__ w,
                             const float* __restrict__ b, float* __restrict__ out){
  int t = blockIdx.x, tid = threadIdx.x;
  int lane = tid & 31, wid = tid >> 5;
  __shared__ float red[16];
  float v = in[(size_t)t*CDIM + tid];
  float s = v, s2 = v*v;
  #pragma unroll
  for (int o=16;o>0;o>>=1){ s += __shfl_xor_sync(0xffffffffu,s,o); s2 += __shfl_xor_sync(0xffffffffu,s2,o); }
  if (lane==0){ red[wid]=s; red[8+wid]=s2; }
  __syncthreads();
  if (tid==0){ float aa=0,cc=0; for(int i=0;i<8;i++){aa+=red[i]; cc+=red[8+i];} red[0]=aa; red[8]=cc; }
  __syncthreads();
  float mean = red[0]*(1.0f/CDIM);
  float var  = red[8]*(1.0f/CDIM) - mean*mean;
  float rstd = rsqrtf(var + 1e-5f);
  out[(size_t)t*CDIM + tid] = (v-mean)*rstd*w[tid] + b[tid];
}

// -------------------- dual LayerNorm over C=256 (two weight sets, one read) ------
__global__ void ln256_dual_kernel(const float* __restrict__ in,
                                  const float* __restrict__ w1, const float* __restrict__ b1,
                                  const float* __restrict__ w2, const float* __restrict__ b2,
                                  float* __restrict__ out1, float* __restrict__ out2){
  int t = blockIdx.x, tid = threadIdx.x;
  int lane = tid & 31, wid = tid >> 5;
  __shared__ float red[16];
  float v = in[(size_t)t*CDIM + tid];
  float s = v, s2 = v*v;
  #pragma unroll
  for (int o=16;o>0;o>>=1){ s += __shfl_xor_sync(0xffffffffu,s,o); s2 += __shfl_xor_sync(0xffffffffu,s2,o); }
  if (lane==0){ red[wid]=s; red[8+wid]=s2; }
  __syncthreads();
  if (tid==0){ float aa=0,cc=0; for(int i=0;i<8;i++){aa+=red[i]; cc+=red[8+i];} red[0]=aa; red[8]=cc; }
  __syncthreads();
  float mean = red[0]*(1.0f/CDIM);
  float var  = red[8]*(1.0f/CDIM) - mean*mean;
  float rstd = rsqrtf(var + 1e-5f);
  float nv = (v-mean)*rstd;
  out1[(size_t)t*CDIM + tid] = nv*w1[tid] + b1[tid];
  out2[(size_t)t*CDIM + tid] = nv*w2[tid] + b2[tid];
}

// -------------------- transpose+pack ctx_w[:, :256] --------------------
__global__ void transpose_w_kernel(const float* __restrict__ ctx_w){
  int o = threadIdx.x, j4 = blockIdx.x;   // 64 blocks x 256 threads
  const float* r = ctx_w + (size_t)o*768 + j4*4;
  g_Wt4[j4*CDIM + o] = make_float4(r[0], r[1], r[2], r[3]);
}

// -------------------- sequential context scan: 1 CTA per batch --------------------
__global__ void scan_kernel(const float* __restrict__ prev, const float* __restrict__ cw,
                            const float* __restrict__ cb){
  int b = blockIdx.x, tid = threadIdx.x;
  int lane = tid & 31, wid = tid >> 5;
  __shared__ float4 ctx4[64];
  __shared__ float red[16];
  __shared__ float stat[2];
  float w_ = cw[tid], b_ = cb[tid];
  ((float*)ctx4)[tid] = prev[b*CDIM + tid];
  __syncthreads();
  for (int t=0; t<SEQ; t++){
    float acc = g_pre[(size_t)(b*SEQ+t)*CDIM + tid];
    float s0=0.f, s1=0.f, s2=0.f, s3=0.f;
    #pragma unroll
    for (int j=0;j<64;j++){
      float4 wv = g_Wt4[j*CDIM + tid];
      float4 c  = ctx4[j];
      s0 = fmaf(wv.x, c.x, s0); s1 = fmaf(wv.y, c.y, s1);
      s2 = fmaf(wv.z, c.z, s2); s3 = fmaf(wv.w, c.w, s3);
    }
    acc += (s0+s1)+(s2+s3);
    float g = gelu_f(acc);
    float rs = g, rq = g*g;
    #pragma unroll
    for (int o=16;o>0;o>>=1){ rs += __shfl_xor_sync(0xffffffffu,rs,o); rq += __shfl_xor_sync(0xffffffffu,rq,o); }
    if (lane==0){ red[wid]=rs; red[8+wid]=rq; }
    __syncthreads();
    if (tid==0){
      float aa=0,cc=0; for(int i=0;i<8;i++){aa+=red[i]; cc+=red[8+i];}
      float mean = aa*(1.0f/CDIM);
      float var  = cc*(1.0f/CDIM) - mean*mean;
      stat[0]=mean; stat[1]=rsqrtf(var + 1e-5f);
    }
    __syncthreads();
    float y = (g - stat[0])*stat[1]*w_ + b_;
    g_x[(size_t)(b*SEQ+t)*CDIM + tid] = y;
    ((float*)ctx4)[tid] = y;
    __syncthreads();
  }
}

// -------------------- RoPE (in-place on q,k; ROT=8, half=4) --------------------
__global__ void rope_kernel(){
  int idx = blockIdx.x*blockDim.x + threadIdx.x;
  if (idx >= NTOK*NHEAD*2) return;
  int qk = idx & 1;
  int h  = (idx>>1) & 7;
  int t  = idx >> 4;
  int pos = t & (SEQ-1);
  float* p = g_qkv + (size_t)t*768 + qk*CDIM + h*HDIM;
  #pragma unroll
  for (int i=0;i<4;i++){
    float inv = 1.0f/powf(10000.0f, (float)(2*i)/8.0f);
    float ang = (float)pos * inv;
    float c = cosf(ang), s = sinf(ang);
    float x0 = p[i], x1 = p[i+4];
    p[i]   = x0*c - x1*s;
    p[i+4] = x1*c + x0*s;
  }
}

// -------------------- causal attention: 1 warp per query row --------------------
__global__ __launch_bounds__(256) void attn_kernel(){
  int qblk = blockIdx.x, h = blockIdx.y, b = blockIdx.z;
  int tid = threadIdx.x, w = tid >> 5, lane = tid & 31;
  __shared__ float Ks[64][33];
  __shared__ float Vs[64][33];
  int q = qblk*8 + w;
  int qtok = b*SEQ + q;
  const float* qp = g_qkv + (size_t)qtok*768 + h*HDIM;
  const float scale = 0.17677669529663687f; // 1/sqrt(32)
  float qr[32];
  #pragma unroll
  for (int d=0;d<32;d++) qr[d] = qp[d]*scale;
  float m = -1e30f, l = 0.f, acc = 0.f;   // acc holds output dim d = lane
  int ntiles = (qblk*8 + 7)/64 + 1;
  for (int tile=0; tile<ntiles; tile++){
    int k0 = tile*64;
    __syncthreads();
    for (int i=tid; i<64*32; i+=256){
      int r = i>>5, d = i&31;
      const float* kp = g_qkv + (size_t)(b*SEQ + k0 + r)*768;
      Ks[r][d] = kp[CDIM   + h*HDIM + d];
      Vs[r][d] = kp[2*CDIM + h*HDIM + d];
    }
    __syncthreads();
    #pragma unroll
    for (int c0=0; c0<64; c0+=32){
      int k = k0 + c0 + lane;
      float s;
      if (k <= q){
        s = 0.f;
        #pragma unroll
        for (int d=0; d<32; d++) s = fmaf(qr[d], Ks[c0+lane][d], s);
      } else s = -1e30f;
      float mc = s;
      #pragma unroll
      for (int o=16;o>0;o>>=1) mc = fmaxf(mc, __shfl_xor_sync(0xffffffffu, mc, o));
      float mnew = fmaxf(m, mc);
      float corr = expf(m - mnew);
      float p = expf(s - mnew);
      acc *= corr; l *= corr;
      float ps = p;
      #pragma unroll
      for (int o=16;o>0;o>>=1) ps += __shfl_xor_sync(0xffffffffu, ps, o);
      l += ps;
      #pragma unroll
      for (int kk=0; kk<32; kk++){
        float pk = __shfl_sync(0xffffffffu, p, kk);
        acc = fmaf(pk, Vs[c0+kk][lane], acc);
      }
      m = mnew;
    }
  }
  g_o[(size_t)qtok*CDIM + h*HDIM + lane] = acc / l;
}

// -------------------- TF32 tensor-core GEMM: C[M,N] = A[M,K] @ B[N,K]^T --------------------
// 128x128x32 tiles, 256 threads = 8 warps (4 along M x 2 along N), warp tile 32x64.
// mma.sync.aligned.m16n8k8 tf32. Smem stride 36 -> conflict-free fragment loads.
#define SMS 36
__global__ __launch_bounds__(256,2) void tgemm_kernel(
    const float* __restrict__ A, int lda,
    const float* __restrict__ B, int ldb,
    const float* __restrict__ bias,
    const float* __restrict__ Res,
    float* __restrict__ C, int ldc,
    int K, int mode){ // mode 0: +bias; 1: gelu(+bias); 2: Res + acc + bias
  __shared__ unsigned As[128*SMS];
  __shared__ unsigned Bs[128*SMS];
  int tid = threadIdx.x;
  int bm = blockIdx.y*128, bn = blockIdx.x*128;
  int w = tid >> 5, lane = tid & 31;
  int wm = (w & 3)*32, wn = (w >> 2)*64;
  int lq = lane >> 2, lr = lane & 3;   // quad row, thread-in-quad

  float acc[2][8][4];
  #pragma unroll
  for (int mi=0;mi<2;mi++)
    #pragma unroll
    for (int ni=0;ni<8;ni++)
      #pragma unroll
      for (int r=0;r<4;r++) acc[mi][ni][r]=0.f;

  for (int kt=0; kt<K; kt+=32){
    #pragma unroll
    for (int i=0;i<4;i++){
      int idx = tid + i*256;
      int r = idx >> 3, c = (idx & 7)*4;
      float4 av = *(const float4*)(A + (size_t)(bm+r)*lda + kt + c);
      float4 bv = *(const float4*)(B + (size_t)(bn+r)*ldb + kt + c);
      As[r*SMS + c+0]=f2tf32(av.x); As[r*SMS + c+1]=f2tf32(av.y);
      As[r*SMS + c+2]=f2tf32(av.z); As[r*SMS + c+3]=f2tf32(av.w);
      Bs[r*SMS + c+0]=f2tf32(bv.x); Bs[r*SMS + c+1]=f2tf32(bv.y);
      Bs[r*SMS + c+2]=f2tf32(bv.z); Bs[r*SMS + c+3]=f2tf32(bv.w);
    }
    __syncthreads();
    #pragma unroll
    for (int kc=0; kc<32; kc+=8){
      unsigned a[2][4], bfr[8][2];
      #pragma unroll
      for (int mi=0;mi<2;mi++){
        int row0 = wm + mi*16 + lq;
        a[mi][0] = As[(row0  )*SMS + kc + lr];
        a[mi][1] = As[(row0+8)*SMS + kc + lr];
        a[mi][2] = As[(row0  )*SMS + kc + lr + 4];
        a[mi][3] = As[(row0+8)*SMS + kc + lr + 4];
      }
      #pragma unroll
      for (int ni=0;ni<8;ni++){
        int nrow = wn + ni*8 + lq;
        bfr[ni][0] = Bs[nrow*SMS + kc + lr];
        bfr[ni][1] = Bs[nrow*SMS + kc + lr + 4];
      }
      #pragma unroll
      for (int mi=0;mi<2;mi++)
        #pragma unroll
        for (int ni=0;ni<8;ni++){
          asm("mma.sync.aligned.m16n8k8.row.col.f32.tf32.tf32.f32 "
              "{%0,%1,%2,%3},{%4,%5,%6,%7},{%8,%9},{%0,%1,%2,%3};"
              : "+f"(acc[mi][ni][0]), "+f"(acc[mi][ni][1]),
                "+f"(acc[mi][ni][2]), "+f"(acc[mi][ni][3])
              : "r"(a[mi][0]), "r"(a[mi][1]), "r"(a[mi][2]), "r"(a[mi][3]),
                "r"(bfr[ni][0]), "r"(bfr[ni][1]));
        }
    }
    __syncthreads();
  }

  // epilogue
  #pragma unroll
  for (int mi=0;mi<2;mi++){
    #pragma unroll
    for (int ni=0;ni<8;ni++){
      int row0 = bm + wm + mi*16 + lq;
      int col  = bn + wn + ni*8 + lr*2;
      float b0=0.f, b1=0.f;
      if (bias){ b0 = bias[col]; b1 = bias[col+1]; }
      #pragma unroll
      for (int half=0; half<2; half++){
        int row = row0 + half*8;
        float v0 = acc[mi][ni][half*2+0] + b0;
        float v1 = acc[mi][ni][half*2+1] + b1;
        if (mode==1){ v0 = gelu_f(v0); v1 = gelu_f(v1); }
        else if (mode==2){
          float2 rr = *(const float2*)(Res + (size_t)row*ldc + col);
          v0 += rr.x; v1 += rr.y;
        }
        float2 ov; ov.x=v0; ov.y=v1;
        *(float2*)(C + (size_t)row*ldc + col) = ov;
      }
    }
  }
}

// -------------------- host launch --------------------
static void* sym_addr_f(const void* symbol){
  void* p = nullptr;
  cudaGetSymbolAddress(&p, symbol);
  return p;
}

extern "C" void kernel_launch(void* const* d_in, const int* in_sizes, int n_in,
                              void* d_out, int out_size){
  (void)in_sizes; (void)n_in; (void)out_size;
  const int*   ids     = (const int*)d_in[0];
  const float* prev    = (const float*)d_in[1];
  const float* embed_w = (const float*)d_in[2];
  const float* en_w    = (const float*)d_in[3];
  const float* en_b    = (const float*)d_in[4];
  const float* ctx_w   = (const float*)d_in[5];
  const float* ctx_b   = (const float*)d_in[6];
  const float* cn_w    = (const float*)d_in[7];
  const float* cn_b    = (const float*)d_in[8];
  const float* ln1_w   = (const float*)d_in[9];
  const float* ln1_b   = (const float*)d_in[10];
  const float* ln2_w   = (const float*)d_in[11];
  const float* ln2_b   = (const float*)d_in[12];
  const float* qkv_w   = (const float*)d_in[13];
  const float* qkv_b   = (const float*)d_in[14];
  const float* ao_w    = (const float*)d_in[15];
  const float* ao_b    = (const float*)d_in[16];
  const float* fc1_w   = (const float*)d_in[17];
  const float* fc1_b   = (const float*)d_in[18];
  const float* fc2_w   = (const float*)d_in[19];
  const float* fc2_b   = (const float*)d_in[20];
  const float* fln_w   = (const float*)d_in[21];
  const float* fln_b   = (const float*)d_in[22];
  const float* out_w   = (const float*)d_in[23];
  float* out = (float*)d_out;

  float* tok = (float*)sym_addr_f(g_tok);
  float* pre = (float*)sym_addr_f(g_pre);
  float* x   = (float*)sym_addr_f(g_x);
  float* a   = (float*)sym_addr_f(g_a);
  float* mm  = (float*)sym_addr_f(g_m);
  float* qkv = (float*)sym_addr_f(g_qkv);
  float* ob  = (float*)sym_addr_f(g_o);
  float* h1  = (float*)sym_addr_f(g_h1);

  // embed + LN, weight transpose, emb-part of the scan matmul
  embed_ln_kernel<<<NTOK,256>>>(ids, embed_w, en_w, en_b);
  transpose_w_kernel<<<64,256>>>(ctx_w);
  tgemm_kernel<<<dim3(CDIM/128, NTOK/128),256>>>(tok,EMB, ctx_w+CDIM,CDIM+EMB, ctx_b, nullptr, pre,CDIM, EMB, 0);
  // sequential context RNN
  scan_kernel<<<BATCH,256>>>(prev, cn_w, cn_b);

  for (int l=0;l<NLAYER;l++){
    ln256_dual_kernel<<<NTOK,256>>>(x, ln1_w+l*CDIM, ln1_b+l*CDIM,
                                    ln2_w+l*CDIM, ln2_b+l*CDIM, a, mm);
    tgemm_kernel<<<dim3(3*CDIM/128, NTOK/128),256>>>(a,CDIM, qkv_w+(size_t)l*3*CDIM*CDIM,CDIM,
                                                     qkv_b+l*3*CDIM, nullptr, qkv,3*CDIM, CDIM, 0);
    rope_kernel<<<(NTOK*NHEAD*2)/256,256>>>();
    attn_kernel<<<dim3(SEQ/8, NHEAD, BATCH),256>>>();
    tgemm_kernel<<<dim3(IDIM/128, NTOK/128),256>>>(mm,CDIM, fc1_w+(size_t)l*IDIM*CDIM,CDIM,
                                                   fc1_b+l*IDIM, nullptr, h1,IDIM, CDIM, 1);
    tgemm_kernel<<<dim3(CDIM/128, NTOK/128),256>>>(ob,CDIM, ao_w+(size_t)l*CDIM*CDIM,CDIM,
                                                   ao_b+l*CDIM, x, x,CDIM, CDIM, 2);
    tgemm_kernel<<<dim3(CDIM/128, NTOK/128),256>>>(h1,IDIM, fc2_w+(size_t)l*CDIM*IDIM,IDIM,
                                                   fc2_b+l*CDIM, x, x,CDIM, IDIM, 2);
  }

  ln256_kernel<<<NTOK,256>>>(x, fln_w, fln_b, a);
  tgemm_kernel<<<dim3(VOCAB/128, NTOK/128),256>>>(a,CDIM, out_w,CDIM, nullptr, nullptr, out,VOCAB, CDIM, 0);
}

// round 16
// speedup vs baseline: 3.1059x; 1.3214x over previous
#include <cuda_runtime.h>
#include <cuda_bf16.h>
#include <math.h>

#define BATCH 4
#define SEQ 1024
#define NTOK (BATCH*SEQ)
#define EMB 512
#define CDIM 256
#define NLAYER 6
#define NHEAD 8
#define HDIM 32
#define IDIM 1024
#define VOCAB 50304
#define SMS 36

// -------------------- scratch (static device allocations) --------------------
__device__ float g_tok[NTOK*EMB];
__device__ float g_pre[NTOK*CDIM];
__device__ float g_x[NTOK*CDIM];
__device__ float g_a[NTOK*CDIM];
__device__ float g_m[NTOK*CDIM];
__device__ float g_qkv[NTOK*3*CDIM];
__device__ float g_o[NTOK*CDIM];
__device__ float g_h1[NTOK*IDIM];
__device__ float4 g_Wt4[64*CDIM];   // ctx_w[:, :256] transposed, packed by 4 j's
// tf32-rounded weights
__device__ float g_ctxw_r[CDIM*(CDIM+EMB)];
__device__ float g_qkvw_r[NLAYER*3*CDIM*CDIM];
__device__ float g_aow_r[NLAYER*CDIM*CDIM];
__device__ float g_fc1w_r[NLAYER*IDIM*CDIM];
__device__ float g_fc2w_r[NLAYER*CDIM*IDIM];
__device__ float g_outw_r[VOCAB*CDIM];

__device__ __forceinline__ float gelu_f(float x){
  float x3 = x*x*x;
  return 0.5f*x*(1.0f + tanhf(0.7978845608028654f*(x + 0.044715f*x3)));
}
__device__ __forceinline__ float tf32r(float f){
  unsigned u; asm("cvt.rna.tf32.f32 %0, %1;" : "=r"(u) : "f"(f));
  return __uint_as_float(u);
}
__device__ __forceinline__ void mma_tf32(float* c, const unsigned* a, unsigned b0, unsigned b1){
  asm("mma.sync.aligned.m16n8k8.row.col.f32.tf32.tf32.f32 "
      "{%0,%1,%2,%3},{%4,%5,%6,%7},{%8,%9},{%0,%1,%2,%3};"
      : "+f"(c[0]),"+f"(c[1]),"+f"(c[2]),"+f"(c[3])
      : "r"(a[0]),"r"(a[1]),"r"(a[2]),"r"(a[3]),"r"(b0),"r"(b1));
}
__device__ __forceinline__ void cpa16(void* smem, const void* gmem){
  unsigned s = (unsigned)__cvta_generic_to_shared(smem);
  asm volatile("cp.async.ca.shared.global [%0], [%1], 16;" :: "r"(s), "l"(gmem));
}

// -------------------- round-to-tf32 copy --------------------
__global__ void round4_kernel(const float4* __restrict__ in, float4* __restrict__ out, int n4){
  int i = blockIdx.x*256 + threadIdx.x;
  if (i < n4){
    float4 v = in[i];
    out[i] = make_float4(tf32r(v.x), tf32r(v.y), tf32r(v.z), tf32r(v.w));
  }
}

// -------------------- embed gather + LayerNorm(E=512) --------------------
__global__ void embed_ln_kernel(const int* __restrict__ ids, const float* __restrict__ emb,
                                const float* __restrict__ w, const float* __restrict__ b){
  int t = blockIdx.x;
  int tid = threadIdx.x;
  int lane = tid & 31, wid = tid >> 5;
  __shared__ float red[16];
  int id = ids[t];
  const float* row = emb + (size_t)id*EMB;
  float v0 = row[tid], v1 = row[tid+256];
  float s = v0+v1, s2 = v0*v0+v1*v1;
  #pragma unroll
  for (int o=16;o>0;o>>=1){ s += __shfl_xor_sync(0xffffffffu,s,o); s2 += __shfl_xor_sync(0xffffffffu,s2,o); }
  if (lane==0){ red[wid]=s; red[8+wid]=s2; }
  __syncthreads();
  if (tid==0){ float aa=0,cc=0; for(int i=0;i<8;i++){aa+=red[i]; cc+=red[8+i];} red[0]=aa; red[8]=cc; }
  __syncthreads();
  float mean = red[0]*(1.0f/EMB);
  float var  = red[8]*(1.0f/EMB) - mean*mean;
  float rstd = rsqrtf(var + 1e-5f);
  g_tok[(size_t)t*EMB + tid]       = tf32r((v0-mean)*rstd*w[tid]     + b[tid]);
  g_tok[(size_t)t*EMB + tid + 256] = tf32r((v1-mean)*rstd*w[tid+256] + b[tid+256]);
}

// -------------------- LayerNorm over C=256 (single output, tf32-rounded) ----------
__global__ void ln256_kernel(const float* __restrict__ in, const float* __restrict__ w,
                             const float* __restrict__ b, float* __restrict__ out){
  int t = blockIdx.x, tid = threadIdx.x;
  int lane = tid & 31, wid = tid >> 5;
  __shared__ float red[16];
  float v = in[(size_t)t*CDIM + tid];
  float s = v, s2 = v*v;
  #pragma unroll
  for (int o=16;o>0;o>>=1){ s += __shfl_xor_sync(0xffffffffu,s,o); s2 += __shfl_xor_sync(0xffffffffu,s2,o); }
  if (lane==0){ red[wid]=s; red[8+wid]=s2; }
  __syncthreads();
  if (tid==0){ float aa=0,cc=0; for(int i=0;i<8;i++){aa+=red[i]; cc+=red[8+i];} red[0]=aa; red[8]=cc; }
  __syncthreads();
  float mean = red[0]*(1.0f/CDIM);
  float var  = red[8]*(1.0f/CDIM) - mean*mean;
  float rstd = rsqrtf(var + 1e-5f);
  out[(size_t)t*CDIM + tid] = tf32r((v-mean)*rstd*w[tid] + b[tid]);
}

// -------------------- dual LayerNorm over C=256 --------------------
__global__ void ln256_dual_kernel(const float* __restrict__ in,
                                  const float* __restrict__ w1, const float* __restrict__ b1,
                                  const float* __restrict__ w2, const float* __restrict__ b2,
                                  float* __restrict__ out1, float* __restrict__ out2){
  int t = blockIdx.x, tid = threadIdx.x;
  int lane = tid & 31, wid = tid >> 5;
  __shared__ float red[16];
  float v = in[(size_t)t*CDIM + tid];
  float s = v, s2 = v*v;
  #pragma unroll
  for (int o=16;o>0;o>>=1){ s += __shfl_xor_sync(0xffffffffu,s,o); s2 += __shfl_xor_sync(0xffffffffu,s2,o); }
  if (lane==0){ red[wid]=s; red[8+wid]=s2; }
  __syncthreads();
  if (tid==0){ float aa=0,cc=0; for(int i=0;i<8;i++){aa+=red[i]; cc+=red[8+i];} red[0]=aa; red[8]=cc; }
  __syncthreads();
  float mean = red[0]*(1.0f/CDIM);
  float var  = red[8]*(1.0f/CDIM) - mean*mean;
  float rstd = rsqrtf(var + 1e-5f);
  float nv = (v-mean)*rstd;
  out1[(size_t)t*CDIM + tid] = tf32r(nv*w1[tid] + b1[tid]);
  out2[(size_t)t*CDIM + tid] = tf32r(nv*w2[tid] + b2[tid]);
}

// -------------------- transpose+pack ctx_w[:, :256] (full fp32 for scan) -----------
__global__ void transpose_w_kernel(const float* __restrict__ ctx_w){
  int o = threadIdx.x, j4 = blockIdx.x;
  const float* r = ctx_w + (size_t)o*768 + j4*4;
  g_Wt4[j4*CDIM + o] = make_float4(r[0], r[1], r[2], r[3]);
}

// -------------------- sequential context scan: 1 CTA per batch --------------------
__global__ void scan_kernel(const float* __restrict__ prev, const float* __restrict__ cw,
                            const float* __restrict__ cb){
  int b = blockIdx.x, tid = threadIdx.x;
  int lane = tid & 31, wid = tid >> 5;
  __shared__ float4 ctx4[64];
  __shared__ float red[16];
  __shared__ float stat[2];
  float w_ = cw[tid], b_ = cb[tid];
  ((float*)ctx4)[tid] = prev[b*CDIM + tid];
  __syncthreads();
  for (int t=0; t<SEQ; t++){
    float acc = g_pre[(size_t)(b*SEQ+t)*CDIM + tid];
    float s0=0.f, s1=0.f, s2=0.f, s3=0.f;
    #pragma unroll
    for (int j=0;j<64;j++){
      float4 wv = g_Wt4[j*CDIM + tid];
      float4 c  = ctx4[j];
      s0 = fmaf(wv.x, c.x, s0); s1 = fmaf(wv.y, c.y, s1);
      s2 = fmaf(wv.z, c.z, s2); s3 = fmaf(wv.w, c.w, s3);
    }
    acc += (s0+s1)+(s2+s3);
    float g = gelu_f(acc);
    float rs = g, rq = g*g;
    #pragma unroll
    for (int o=16;o>0;o>>=1){ rs += __shfl_xor_sync(0xffffffffu,rs,o); rq += __shfl_xor_sync(0xffffffffu,rq,o); }
    if (lane==0){ red[wid]=rs; red[8+wid]=rq; }
    __syncthreads();
    if (tid==0){
      float aa=0,cc=0; for(int i=0;i<8;i++){aa+=red[i]; cc+=red[8+i];}
      float mean = aa*(1.0f/CDIM);
      float var  = cc*(1.0f/CDIM) - mean*mean;
      stat[0]=mean; stat[1]=rsqrtf(var + 1e-5f);
    }
    __syncthreads();
    float y = (g - stat[0])*stat[1]*w_ + b_;
    g_x[(size_t)(b*SEQ+t)*CDIM + tid] = y;
    ((float*)ctx4)[tid] = y;
    __syncthreads();
  }
}

// -------------------- RoPE (in-place on q,k; ROT=8, half=4) --------------------
__global__ void rope_kernel(){
  int idx = blockIdx.x*blockDim.x + threadIdx.x;
  if (idx >= NTOK*NHEAD*2) return;
  int qk = idx & 1;
  int h  = (idx>>1) & 7;
  int t  = idx >> 4;
  int pos = t & (SEQ-1);
  float* p = g_qkv + (size_t)t*768 + qk*CDIM + h*HDIM;
  #pragma unroll
  for (int i=0;i<4;i++){
    float inv = 1.0f/powf(10000.0f, (float)(2*i)/8.0f);
    float ang = (float)pos * inv;
    float c = cosf(ang), s = sinf(ang);
    float x0 = p[i], x1 = p[i+4];
    p[i]   = x0*c - x1*s;
    p[i+4] = x1*c + x0*s;
  }
}

// -------------------- tensor-core flash attention --------------------
// CTA = (qtile 64, head, batch); 4 warps, warp handles 16 q-rows.
// S = Q K^T via tf32 mma; online softmax in c-fragment layout; P -> smem -> A frags; O += P V.
__global__ __launch_bounds__(128) void attn_mma_kernel(){
  int qt = blockIdx.x, h = blockIdx.y, b = blockIdx.z;
  int tid = threadIdx.x, w = tid>>5, lane = tid&31;
  int lq = lane>>2, lr = lane&3;
  __shared__ float Qs[64*SMS];
  __shared__ float Ks[64*SMS];
  __shared__ float Vs[32*68];        // transposed: [d][key]
  __shared__ float Ps[4][16*68];     // per-warp P tile [16 q][64 key]
  const float scale = 0.17677669529663687f;  // 1/sqrt(32)
  int base_q = b*SEQ + qt*64;

  // load Q tile (scaled, tf32-rounded)
  for (int i=tid; i<64*8; i+=128){
    int r = i>>3, c4 = (i&7)*4;
    const float* qp = g_qkv + (size_t)(base_q + r)*768 + h*HDIM + c4;
    float4 v = *(const float4*)qp;
    Qs[r*SMS + c4+0] = tf32r(v.x*scale);
    Qs[r*SMS + c4+1] = tf32r(v.y*scale);
    Qs[r*SMS + c4+2] = tf32r(v.z*scale);
    Qs[r*SMS + c4+3] = tf32r(v.w*scale);
  }
  __syncthreads();

  // Q fragments (constant over k-tiles)
  unsigned qf[4][4];
  #pragma unroll
  for (int kc=0; kc<4; kc++){
    qf[kc][0] = __float_as_uint(Qs[(w*16+lq  )*SMS + kc*8 + lr]);
    qf[kc][1] = __float_as_uint(Qs[(w*16+lq+8)*SMS + kc*8 + lr]);
    qf[kc][2] = __float_as_uint(Qs[(w*16+lq  )*SMS + kc*8 + lr+4]);
    qf[kc][3] = __float_as_uint(Qs[(w*16+lq+8)*SMS + kc*8 + lr+4]);
  }

  float m0=-1e30f, m1=-1e30f, l0=0.f, l1=0.f;
  float o[4][4];
  #pragma unroll
  for (int i=0;i<4;i++){ o[i][0]=0.f; o[i][1]=0.f; o[i][2]=0.f; o[i][3]=0.f; }

  for (int kt=0; kt<=qt; kt++){
    // load K (row-major) and V (transposed) tiles, tf32-rounded
    for (int i=tid; i<64*8; i+=128){
      int r = i>>3, c4 = (i&7)*4;
      const float* kp = g_qkv + (size_t)(b*SEQ + kt*64 + r)*768 + CDIM + h*HDIM + c4;
      float4 v = *(const float4*)kp;
      Ks[r*SMS + c4+0]=tf32r(v.x); Ks[r*SMS + c4+1]=tf32r(v.y);
      Ks[r*SMS + c4+2]=tf32r(v.z); Ks[r*SMS + c4+3]=tf32r(v.w);
      const float* vp = kp + CDIM;
      float4 u = *(const float4*)vp;
      Vs[(c4+0)*68 + r]=tf32r(u.x); Vs[(c4+1)*68 + r]=tf32r(u.y);
      Vs[(c4+2)*68 + r]=tf32r(u.z); Vs[(c4+3)*68 + r]=tf32r(u.w);
    }
    __syncthreads();

    // S = Q K^T  (16 x 64 per warp)
    float s[8][4];
    #pragma unroll
    for (int nt=0; nt<8; nt++){
      s[nt][0]=0.f; s[nt][1]=0.f; s[nt][2]=0.f; s[nt][3]=0.f;
      #pragma unroll
      for (int kc=0; kc<4; kc++){
        unsigned b0 = __float_as_uint(Ks[(nt*8+lq)*SMS + kc*8 + lr]);
        unsigned b1 = __float_as_uint(Ks[(nt*8+lq)*SMS + kc*8 + lr+4]);
        mma_tf32(s[nt], qf[kc], b0, b1);
      }
    }
    // causal mask on diagonal tile
    if (kt == qt){
      int q0 = w*16 + lq, q1 = q0 + 8;
      #pragma unroll
      for (int nt=0; nt<8; nt++){
        int c0 = nt*8 + 2*lr, c1 = c0+1;
        if (c0 > q0) s[nt][0] = -1e30f;
        if (c1 > q0) s[nt][1] = -1e30f;
        if (c0 > q1) s[nt][2] = -1e30f;
        if (c1 > q1) s[nt][3] = -1e30f;
      }
    }
    // row maxima (rows lq and lq+8)
    float mt0=-1e30f, mt1=-1e30f;
    #pragma unroll
    for (int nt=0; nt<8; nt++){
      mt0 = fmaxf(mt0, fmaxf(s[nt][0], s[nt][1]));
      mt1 = fmaxf(mt1, fmaxf(s[nt][2], s[nt][3]));
    }
    mt0 = fmaxf(mt0, __shfl_xor_sync(0xffffffffu, mt0, 1));
    mt0 = fmaxf(mt0, __shfl_xor_sync(0xffffffffu, mt0, 2));
    mt1 = fmaxf(mt1, __shfl_xor_sync(0xffffffffu, mt1, 1));
    mt1 = fmaxf(mt1, __shfl_xor_sync(0xffffffffu, mt1, 2));
    float mn0 = fmaxf(m0, mt0), mn1 = fmaxf(m1, mt1);
    float cr0 = __expf(m0 - mn0), cr1 = __expf(m1 - mn1);
    float rs0 = 0.f, rs1 = 0.f;
    #pragma unroll
    for (int nt=0; nt<8; nt++){
      float p0 = __expf(s[nt][0]-mn0), p1 = __expf(s[nt][1]-mn0);
      float p2 = __expf(s[nt][2]-mn1), p3 = __expf(s[nt][3]-mn1);
      rs0 += p0+p1; rs1 += p2+p3;
      Ps[w][ lq   *68 + nt*8 + 2*lr  ] = tf32r(p0);
      Ps[w][ lq   *68 + nt*8 + 2*lr+1] = tf32r(p1);
      Ps[w][(lq+8)*68 + nt*8 + 2*lr  ] = tf32r(p2);
      Ps[w][(lq+8)*68 + nt*8 + 2*lr+1] = tf32r(p3);
    }
    rs0 += __shfl_xor_sync(0xffffffffu, rs0, 1);
    rs0 += __shfl_xor_sync(0xffffffffu, rs0, 2);
    rs1 += __shfl_xor_sync(0xffffffffu, rs1, 1);
    rs1 += __shfl_xor_sync(0xffffffffu, rs1, 2);
    l0 = l0*cr0 + rs0;  l1 = l1*cr1 + rs1;
    m0 = mn0; m1 = mn1;
    #pragma unroll
    for (int nt2=0; nt2<4; nt2++){
      o[nt2][0]*=cr0; o[nt2][1]*=cr0; o[nt2][2]*=cr1; o[nt2][3]*=cr1;
    }
    __syncwarp();
    // O += P V
    #pragma unroll
    for (int kc2=0; kc2<8; kc2++){
      unsigned a[4];
      a[0] = __float_as_uint(Ps[w][ lq   *68 + kc2*8 + lr  ]);
      a[1] = __float_as_uint(Ps[w][(lq+8)*68 + kc2*8 + lr  ]);
      a[2] = __float_as_uint(Ps[w][ lq   *68 + kc2*8 + lr+4]);
      a[3] = __float_as_uint(Ps[w][(lq+8)*68 + kc2*8 + lr+4]);
      #pragma unroll
      for (int nt2=0; nt2<4; nt2++){
        unsigned b0 = __float_as_uint(Vs[(nt2*8+lq)*68 + kc2*8 + lr]);
        unsigned b1 = __float_as_uint(Vs[(nt2*8+lq)*68 + kc2*8 + lr+4]);
        mma_tf32(o[nt2], a, b0, b1);
      }
    }
    __syncthreads();
  }

  // epilogue: normalize + tf32-round (feeds ao GEMM)
  float i0 = 1.f/l0, i1 = 1.f/l1;
  size_t go0 = (size_t)(base_q + w*16 + lq)*CDIM + h*HDIM;
  size_t go1 = go0 + (size_t)8*CDIM;
  #pragma unroll
  for (int nt2=0; nt2<4; nt2++){
    int d = nt2*8 + 2*lr;
    g_o[go0 + d  ] = tf32r(o[nt2][0]*i0);
    g_o[go0 + d+1] = tf32r(o[nt2][1]*i0);
    g_o[go1 + d  ] = tf32r(o[nt2][2]*i1);
    g_o[go1 + d+1] = tf32r(o[nt2][3]*i1);
  }
}

// -------------------- TF32 GEMM, cp.async double-buffered --------------------
// C[M,N] = A[M,K] @ B[N,K]^T. Inputs must be tf32-rounded fp32.
__global__ __launch_bounds__(256,2) void tgemm_kernel(
    const float* __restrict__ A, int lda,
    const float* __restrict__ B, int ldb,
    const float* __restrict__ bias,
    const float* __restrict__ Res,
    float* __restrict__ C, int ldc,
    int K, int mode){ // 0: +bias; 1: gelu(+bias), tf32-round; 2: Res + acc + bias
  extern __shared__ float smbuf[];
  float* As = smbuf;                 // [2][128*SMS]
  float* Bs = smbuf + 2*128*SMS;
  int tid = threadIdx.x;
  int bm = blockIdx.y*128, bn = blockIdx.x*128;
  int w = tid >> 5, lane = tid & 31;
  int wm = (w & 3)*32, wn = (w >> 2)*64;
  int lq = lane >> 2, lr = lane & 3;

  float acc[2][8][4];
  #pragma unroll
  for (int mi=0;mi<2;mi++)
    #pragma unroll
    for (int ni=0;ni<8;ni++)
      #pragma unroll
      for (int r=0;r<4;r++) acc[mi][ni][r]=0.f;

  auto load_tile = [&](int buf, int kt){
    #pragma unroll
    for (int i=0;i<4;i++){
      int idx = tid + i*256;
      int r = idx >> 3, c = (idx & 7)*4;
      cpa16(&As[buf*128*SMS + r*SMS + c], A + (size_t)(bm+r)*lda + kt + c);
      cpa16(&Bs[buf*128*SMS + r*SMS + c], B + (size_t)(bn+r)*ldb + kt + c);
    }
  };

  load_tile(0, 0);
  asm volatile("cp.async.commit_group;");
  int nk = K >> 5;
  for (int t=0; t<nk; t++){
    int cur = t & 1;
    if (t+1 < nk) load_tile(1-cur, (t+1)*32);
    asm volatile("cp.async.commit_group;");
    asm volatile("cp.async.wait_group 1;");
    __syncthreads();
    const float* Ab = As + cur*128*SMS;
    const float* Bb = Bs + cur*128*SMS;
    #pragma unroll
    for (int kc=0; kc<32; kc+=8){
      unsigned a[2][4], bfr[8][2];
      #pragma unroll
      for (int mi=0;mi<2;mi++){
        int row0 = wm + mi*16 + lq;
        a[mi][0] = __float_as_uint(Ab[(row0  )*SMS + kc + lr]);
        a[mi][1] = __float_as_uint(Ab[(row0+8)*SMS + kc + lr]);
        a[mi][2] = __float_as_uint(Ab[(row0  )*SMS + kc + lr + 4]);
        a[mi][3] = __float_as_uint(Ab[(row0+8)*SMS + kc + lr + 4]);
      }
      #pragma unroll
      for (int ni=0;ni<8;ni++){
        int nrow = wn + ni*8 + lq;
        bfr[ni][0] = __float_as_uint(Bb[nrow*SMS + kc + lr]);
        bfr[ni][1] = __float_as_uint(Bb[nrow*SMS + kc + lr + 4]);
      }
      #pragma unroll
      for (int mi=0;mi<2;mi++)
        #pragma unroll
        for (int ni=0;ni<8;ni++)
          mma_tf32(acc[mi][ni], a[mi], bfr[ni][0], bfr[ni][1]);
    }
    __syncthreads();
  }

  #pragma unroll
  for (int mi=0;mi<2;mi++){
    #pragma unroll
    for (int ni=0;ni<8;ni++){
      int row0 = bm + wm + mi*16 + lq;
      int col  = bn + wn + ni*8 + lr*2;
      float b0=0.f, b1=0.f;
      if (bias){ b0 = bias[col]; b1 = bias[col+1]; }
      #pragma unroll
      for (int half=0; half<2; half++){
        int row = row0 + half*8;
        float v0 = acc[mi][ni][half*2+0] + b0;
        float v1 = acc[mi][ni][half*2+1] + b1;
        if (mode==1){ v0 = tf32r(gelu_f(v0)); v1 = tf32r(gelu_f(v1)); }
        else if (mode==2){
          float2 rr = *(const float2*)(Res + (size_t)row*ldc + col);
          v0 += rr.x; v1 += rr.y;
        }
        float2 ov; ov.x=v0; ov.y=v1;
        *(float2*)(C + (size_t)row*ldc + col) = ov;
      }
    }
  }
}

// -------------------- host launch --------------------
static void* sym_addr_f(const void* symbol){
  void* p = nullptr;
  cudaGetSymbolAddress(&p, symbol);
  return p;
}
static void round_arr(const float* in, float* out, int n){
  int n4 = n/4;
  round4_kernel<<<(n4+255)/256, 256>>>((const float4*)in, (float4*)out, n4);
}

extern "C" void kernel_launch(void* const* d_in, const int* in_sizes, int n_in,
                              void* d_out, int out_size){
  (void)in_sizes; (void)n_in; (void)out_size;
  const int*   ids     = (const int*)d_in[0];
  const float* prev    = (const float*)d_in[1];
  const float* embed_w = (const float*)d_in[2];
  const float* en_w    = (const float*)d_in[3];
  const float* en_b    = (const float*)d_in[4];
  const float* ctx_w   = (const float*)d_in[5];
  const float* ctx_b   = (const float*)d_in[6];
  const float* cn_w    = (const float*)d_in[7];
  const float* cn_b    = (const float*)d_in[8];
  const float* ln1_w   = (const float*)d_in[9];
  const float* ln1_b   = (const float*)d_in[10];
  const float* ln2_w   = (const float*)d_in[11];
  const float* ln2_b   = (const float*)d_in[12];
  const float* qkv_w   = (const float*)d_in[13];
  const float* qkv_b   = (const float*)d_in[14];
  const float* ao_w    = (const float*)d_in[15];
  const float* ao_b    = (const float*)d_in[16];
  const float* fc1_w   = (const float*)d_in[17];
  const float* fc1_b   = (const float*)d_in[18];
  const float* fc2_w   = (const float*)d_in[19];
  const float* fc2_b   = (const float*)d_in[20];
  const float* fln_w   = (const float*)d_in[21];
  const float* fln_b   = (const float*)d_in[22];
  const float* out_w   = (const float*)d_in[23];
  float* out = (float*)d_out;

  float* tok = (float*)sym_addr_f(g_tok);
  float* pre = (float*)sym_addr_f(g_pre);
  float* x   = (float*)sym_addr_f(g_x);
  float* a   = (float*)sym_addr_f(g_a);
  float* mm  = (float*)sym_addr_f(g_m);
  float* ob  = (float*)sym_addr_f(g_o);
  float* h1  = (float*)sym_addr_f(g_h1);
  float* ctxw_r = (float*)sym_addr_f(g_ctxw_r);
  float* qkvw_r = (float*)sym_addr_f(g_qkvw_r);
  float* aow_r  = (float*)sym_addr_f(g_aow_r);
  float* fc1w_r = (float*)sym_addr_f(g_fc1w_r);
  float* fc2w_r = (float*)sym_addr_f(g_fc2w_r);
  float* outw_r = (float*)sym_addr_f(g_outw_r);

  const int GSM = 2*2*128*SMS*4;  // 73728 B dynamic smem
  cudaFuncSetAttribute(tgemm_kernel, cudaFuncAttributeMaxDynamicSharedMemorySize, GSM);

  // pre-round all GEMM weight operands to tf32 grid
  round_arr(ctx_w, ctxw_r, CDIM*(CDIM+EMB));
  round_arr(qkv_w, qkvw_r, NLAYER*3*CDIM*CDIM);
  round_arr(ao_w,  aow_r,  NLAYER*CDIM*CDIM);
  round_arr(fc1_w, fc1w_r, NLAYER*IDIM*CDIM);
  round_arr(fc2_w, fc2w_r, NLAYER*CDIM*IDIM);
  round_arr(out_w, outw_r, VOCAB*CDIM);

  embed_ln_kernel<<<NTOK,256>>>(ids, embed_w, en_w, en_b);
  transpose_w_kernel<<<64,256>>>(ctx_w);
  tgemm_kernel<<<dim3(CDIM/128, NTOK/128),256,GSM>>>(tok,EMB, ctxw_r+CDIM,CDIM+EMB, ctx_b, nullptr, pre,CDIM, EMB, 0);
  scan_kernel<<<BATCH,256>>>(prev, cn_w, cn_b);

  for (int l=0;l<NLAYER;l++){
    ln256_dual_kernel<<<NTOK,256>>>(x, ln1_w+l*CDIM, ln1_b+l*CDIM,
                                    ln2_w+l*CDIM, ln2_b+l*CDIM, a, mm);
    tgemm_kernel<<<dim3(3*CDIM/128, NTOK/128),256,GSM>>>(a,CDIM, qkvw_r+(size_t)l*3*CDIM*CDIM,CDIM,
                                                         qkv_b+l*3*CDIM, nullptr, (float*)sym_addr_f(g_qkv),3*CDIM, CDIM, 0);
    rope_kernel<<<(NTOK*NHEAD*2)/256,256>>>();
    attn_mma_kernel<<<dim3(SEQ/64, NHEAD, BATCH),128>>>();
    tgemm_kernel<<<dim3(IDIM/128, NTOK/128),256,GSM>>>(mm,CDIM, fc1w_r+(size_t)l*IDIM*CDIM,CDIM,
                                                       fc1_b+l*IDIM, nullptr, h1,IDIM, CDIM, 1);
    tgemm_kernel<<<dim3(CDIM/128, NTOK/128),256,GSM>>>(ob,CDIM, aow_r+(size_t)l*CDIM*CDIM,CDIM,
                                                       ao_b+l*CDIM, x, x,CDIM, CDIM, 2);
    tgemm_kernel<<<dim3(CDIM/128, NTOK/128),256,GSM>>>(h1,IDIM, fc2w_r+(size_t)l*CDIM*IDIM,IDIM,
                                                       fc2_b+l*CDIM, x, x,CDIM, IDIM, 2);
  }

  ln256_kernel<<<NTOK,256>>>(x, fln_w, fln_b, a);
  tgemm_kernel<<<dim3(VOCAB/128, NTOK/128),256,GSM>>>(a,CDIM, outw_r,CDIM, nullptr, nullptr, out,VOCAB, CDIM, 0);
}